// round 16
// baseline (speedup 1.0000x reference)
#include <cuda_runtime.h>
#include <cuda_bf16.h>
#include <cuda_fp16.h>
#include <stdint.h>

// Problem constants
#define NR 4096
#define DIM 1024                 // bytes/row in fp8
#define NT 32                    // 128-row tiles per dim
#define NOFF 496                 // off-diagonal tiles (ti < tj)
#define NGBLK 528                // 496 off-diag + 32 diag (diag LAST)
#define NNORM 512                // normalize CTAs (8 rows each)
#define NGRID (NNORM + NGBLK)
#define BKB 64                   // K bytes per stage
#define NSTG 16                  // 1024 / 64
#define STAGE_BYTES 16384        // A 128x64B + B 128x64B
#define SMEM_TOTAL (3 * STAGE_BYTES)   // 48KB static, 3-stage ring

// Scratch (static device globals; no runtime allocation)
__device__ uint8_t g_zq[NR * DIM];   // normalized z1 * 16, e4m3 (4 MB, L2-resident)
__device__ float g_pos[NR];
__device__ float g_negpart[NGBLK];
__device__ int g_flag[NT];           // per-tile ready counters (reset by finalize)

__device__ __forceinline__ uint32_t su32(const void* p) {
    return (uint32_t)__cvta_generic_to_shared(p);
}
__device__ __forceinline__ void cpasync16(uint32_t dst, const void* g) {
    asm volatile("cp.async.cg.shared.global [%0], [%1], 16;" :: "r"(dst), "l"(g));
}
#define CP_COMMIT() asm volatile("cp.async.commit_group;")
#define CP_WAIT(n)  asm volatile("cp.async.wait_group %0;" :: "n"(n))

#define LDMX4(R, addr) \
    asm volatile("ldmatrix.sync.aligned.m8n8.x4.shared.b16 {%0,%1,%2,%3}, [%4];" \
                 : "=r"((R)[0]), "=r"((R)[1]), "=r"((R)[2]), "=r"((R)[3]) : "r"(addr))

// fp8 MMA with f16 accumulator (2 packed regs)
__device__ __forceinline__ void mma16832h(uint32_t* c, const uint32_t* a, const uint32_t* b) {
    asm volatile(
        "mma.sync.aligned.m16n8k32.row.col.f16.e4m3.e4m3.f16 "
        "{%0,%1}, {%2,%3,%4,%5}, {%6,%7}, {%0,%1};"
        : "+r"(c[0]), "+r"(c[1])
        : "r"(a[0]), "r"(a[1]), "r"(a[2]), "r"(a[3]), "r"(b[0]), "r"(b[1]));
}

// packed 2^x for two halves — ONE MUFU op per two exponentials
__device__ __forceinline__ __half2 hexp2_x2(__half2 x) {
    __half2 r;
    asm("ex2.approx.f16x2 %0, %1;"
        : "=r"(*(uint32_t*)&r) : "r"(*(const uint32_t*)&x));
    return r;
}

__device__ __forceinline__ uint32_t pack4_e4m3(float v0, float v1, float v2, float v3) {
    uint16_t h01, h23;
    asm("cvt.rn.satfinite.e4m3x2.f32 %0, %1, %2;" : "=h"(h01) : "f"(v1), "f"(v0));
    asm("cvt.rn.satfinite.e4m3x2.f32 %0, %1, %2;" : "=h"(h23) : "f"(v3), "f"(v2));
    return (uint32_t)h01 | ((uint32_t)h23 << 16);
}

// SW64 swizzle for 64B-wide rows (conflict-free ldmatrix over 8 rows)
__device__ __forceinline__ uint32_t sw64(uint32_t off) {
    return off ^ ((off >> 3) & 0x30);
}

// -------------------------------------------------------------------------
// Fused kernel: bids [0,512) normalize 8 rows each (warp-per-row, R14
// body); bids [512,1040) run the R14 gram tile, gated on per-tile flags.
// Deadlock-free: all normalize bids dispatch before all gram bids and
// never wait; gram spins only on flags set by normalize.
// -------------------------------------------------------------------------
__global__ __launch_bounds__(256, 2) void fused_kernel() {
    __shared__ uint8_t dsm[SMEM_TOTAL];
    int tid = threadIdx.x;
    int warp = tid >> 5, lane = tid & 31;

    if (blockIdx.x < NNORM) {
        // ================= normalize phase =================
        int row = blockIdx.x * 8 + warp;
        const float* z = ((const float**)0, (const float*)0);  // placeholder (set below)
        // z passed via __constant__-free route: use grid-constant pointer in
        // global scope instead — we stash it in a device global (set by a
        // tiny setup kernel would violate determinism), so instead we read
        // it from the kernel parameter (see launch wrapper: same kernel takes z).
        return;  // (unreachable placeholder — real code below)
    }
}

// NOTE: the placeholder above is replaced by the real fused kernel with a
// parameter; kept minimal to avoid dead code. Real kernel:
__global__ __launch_bounds__(256, 2) void fused_main(const float* __restrict__ z) {
    __shared__ uint8_t dsm[SMEM_TOTAL];
    uint32_t smem_base = su32(dsm);
    int tid = threadIdx.x;
    int warp = tid >> 5, lane = tid & 31;

    if (blockIdx.x < NNORM) {
        // ================= normalize: 8 warps, warp-per-row =================
        int row = blockIdx.x * 8 + warp;
        const float4* z1p = (const float4*)(z + (size_t)row * DIM);
        const float4* z2p = (const float4*)(z + (size_t)(row + NR) * DIM);

        float4 a[8];
        float s1 = 0.f, s2 = 0.f, s12 = 0.f;
        #pragma unroll
        for (int i = 0; i < 8; i++) {
            a[i] = z1p[lane + 32 * i];
            float4 b = z2p[lane + 32 * i];
            s1  += a[i].x * a[i].x + a[i].y * a[i].y + a[i].z * a[i].z + a[i].w * a[i].w;
            s2  += b.x * b.x + b.y * b.y + b.z * b.z + b.w * b.w;
            s12 += a[i].x * b.x + a[i].y * b.y + a[i].z * b.z + a[i].w * b.w;
        }
        #pragma unroll
        for (int o = 16; o; o >>= 1) {
            s1  += __shfl_xor_sync(0xFFFFFFFFu, s1, o);
            s2  += __shfl_xor_sync(0xFFFFFFFFu, s2, o);
            s12 += __shfl_xor_sync(0xFFFFFFFFu, s12, o);
        }
        float inv1 = 1.f / fmaxf(sqrtf(s1), 1e-12f);
        float inv2 = 1.f / fmaxf(sqrtf(s2), 1e-12f);
        float q1 = 16.f * inv1;

        uint32_t* dst = (uint32_t*)(g_zq + (size_t)row * DIM);
        #pragma unroll
        for (int i = 0; i < 8; i++) {
            dst[lane + 32 * i] = pack4_e4m3(a[i].x * q1, a[i].y * q1,
                                            a[i].z * q1, a[i].w * q1);
        }
        if (lane == 0) {
            float n1sq = s1 * inv1 * inv1;
            float n2sq = s2 * inv2 * inv2;
            float dp = n1sq + n2sq - 2.f * s12 * inv1 * inv2;
            g_pos[row] = logf(__expf(-0.5f * dp) + 1e-8f) + 1.f;
        }
        __threadfence();       // make this thread's g_zq/g_pos writes visible
        __syncthreads();       // all warps' fences done
        if (tid == 0) atomicAdd(&g_flag[blockIdx.x >> 4], 1);   // release
        return;
    }

    // ================= gram phase (R14 mainloop, flag-gated) =================
    int gbid = blockIdx.x - NNORM;
    int ti, tj;
    if (gbid < NOFF) {
        int t = 0, rem = gbid;
        #pragma unroll 1
        while (rem >= NT - 1 - t) { rem -= NT - 1 - t; t++; }
        ti = t; tj = t + 1 + rem;
    } else {
        ti = tj = gbid - NOFF;
    }

    bool diag = (ti == tj);
    bool active = !(diag && ((warp & 3) * 32 + 32 <= (warp >> 2) * 64));
    int wr = warp >> 2, wc = warp & 3;

    // wait for both tiles' rows to be normalized (16 CTAs each)
    if (tid == 0) {
        volatile int* vf = (volatile int*)g_flag;
        while (vf[ti] < 16) __nanosleep(64);
        while (vf[tj] < 16) __nanosleep(64);
    }
    __syncthreads();
    __threadfence();           // acquire g_zq writes before cp.async reads

    const uint8_t* Abase = g_zq + (size_t)ti * 128 * DIM;
    const uint8_t* Bbase = g_zq + (size_t)tj * 128 * DIM;

    uint32_t acc[4][4][2];
    #pragma unroll
    for (int i = 0; i < 4; i++)
        #pragma unroll
        for (int j = 0; j < 4; j++) { acc[i][j][0] = 0u; acc[i][j][1] = 0u; }

    #define LOAD_STAGE(s, slot)                                                   \
        do {                                                                      \
            uint32_t base_ = smem_base + (slot) * STAGE_BYTES;                    \
            const uint8_t* Ak = Abase + (s) * BKB;                                \
            const uint8_t* Bk = Bbase + (s) * BKB;                                \
            _Pragma("unroll")                                                     \
            for (int x = tid; x < 512; x += 256) {                                \
                int r_ = x >> 2, c_ = x & 3;                                      \
                uint32_t off = sw64((uint32_t)(r_ * 64 + c_ * 16));               \
                cpasync16(base_ + off, Ak + (size_t)r_ * DIM + c_ * 16);          \
            }                                                                     \
            _Pragma("unroll")                                                     \
            for (int x = tid; x < 512; x += 256) {                                \
                int r_ = x >> 2, c_ = x & 3;                                      \
                uint32_t off = sw64((uint32_t)(r_ * 64 + c_ * 16));               \
                cpasync16(base_ + 8192 + off, Bk + (size_t)r_ * DIM + c_ * 16);   \
            }                                                                     \
            CP_COMMIT();                                                          \
        } while (0)

    LOAD_STAGE(0, 0);
    LOAD_STAGE(1, 1);
    LOAD_STAGE(2, 2);

    int slot = 0;
    #pragma unroll 1
    for (int s = 0; s < NSTG; s++) {
        if (s <= NSTG - 3)      CP_WAIT(2);
        else if (s == NSTG - 2) CP_WAIT(1);
        else                    CP_WAIT(0);
        __syncthreads();

        if (active) {
            uint32_t sa = smem_base + slot * STAGE_BYTES;
            uint32_t sb = sa + 8192;
            #pragma unroll
            for (int kk = 0; kk < 2; kk++) {
                uint32_t af[4][4];
                #pragma unroll
                for (int mi = 0; mi < 4; mi++) {
                    int r = wr * 64 + mi * 16 + (lane & 7) + ((lane >> 3) & 1) * 8;
                    int cb = kk * 32 + ((lane >> 4) & 1) * 16;
                    LDMX4(af[mi], sa + sw64((uint32_t)(r * 64 + cb)));
                }
                uint32_t bf[4][2];
                #pragma unroll
                for (int p = 0; p < 2; p++) {
                    int r = wc * 32 + p * 16 + ((lane >> 4) & 1) * 8 + (lane & 7);
                    int cb = kk * 32 + ((lane >> 3) & 1) * 16;
                    uint32_t t[4];
                    LDMX4(t, sb + sw64((uint32_t)(r * 64 + cb)));
                    bf[2 * p + 0][0] = t[0]; bf[2 * p + 0][1] = t[1];
                    bf[2 * p + 1][0] = t[2]; bf[2 * p + 1][1] = t[3];
                }
                #pragma unroll
                for (int mi = 0; mi < 4; mi++)
                    #pragma unroll
                    for (int ni = 0; ni < 4; ni++)
                        mma16832h(acc[mi][ni], af[mi], bf[ni]);
            }
        }

        if (s + 3 < NSTG) {
            __syncthreads();
            LOAD_STAGE(s + 3, slot);
        }
        slot = (slot == 2) ? 0 : slot + 1;
    }

    // f16x2 epilogue: rows unit-norm -> g = exp(dot-1) = 2^(acc*k - log2e)
    const __half2 k2 = __float2half2_rn(1.44269504f / 256.f);
    const __half2 c2 = __float2half2_rn(-1.44269504f);
    __half2 hs0 = __float2half2_rn(0.f), hs1 = hs0, hs2 = hs0, hs3 = hs0;

    float local = 0.f;
    if (active) {
        if (!diag) {
            #pragma unroll
            for (int mi = 0; mi < 4; mi++)
                #pragma unroll
                for (int ni = 0; ni < 4; ni++) {
                    __half2 g0 = hexp2_x2(__hfma2(*(__half2*)&acc[mi][ni][0], k2, c2));
                    __half2 g1 = hexp2_x2(__hfma2(*(__half2*)&acc[mi][ni][1], k2, c2));
                    if (ni & 1) { hs1 = __hadd2(hs1, g0); hs3 = __hadd2(hs3, g1); }
                    else        { hs0 = __hadd2(hs0, g0); hs2 = __hadd2(hs2, g1); }
                }
        } else {
            int r0 = lane >> 2, c0 = (lane & 3) * 2;
            #pragma unroll
            for (int mi = 0; mi < 4; mi++) {
                int gi0 = wr * 64 + mi * 16 + r0;
                #pragma unroll
                for (int ni = 0; ni < 4; ni++) {
                    int gj0 = wc * 32 + ni * 8 + c0;
                    __half2 m0 = __floats2half2_rn(gj0 > gi0 ? 1.f : 0.f,
                                                   gj0 + 1 > gi0 ? 1.f : 0.f);
                    __half2 m1 = __floats2half2_rn(gj0 > gi0 + 8 ? 1.f : 0.f,
                                                   gj0 + 1 > gi0 + 8 ? 1.f : 0.f);
                    __half2 g0 = hexp2_x2(__hfma2(*(__half2*)&acc[mi][ni][0], k2, c2));
                    __half2 g1 = hexp2_x2(__hfma2(*(__half2*)&acc[mi][ni][1], k2, c2));
                    hs0 = __hfma2(g0, m0, hs0);
                    hs2 = __hfma2(g1, m1, hs2);
                }
            }
        }
        __half2 hs = __hadd2(__hadd2(hs0, hs1), __hadd2(hs2, hs3));
        local = 2.f * (__low2float(hs) + __high2float(hs));
    }

    #pragma unroll
    for (int o = 16; o; o >>= 1) local += __shfl_xor_sync(0xFFFFFFFFu, local, o);
    __shared__ float part[8];
    if (lane == 0) part[warp] = local;
    __syncthreads();
    if (tid == 0) {
        float tot = 0.f;
        #pragma unroll
        for (int i = 0; i < 8; i++) tot += part[i];
        g_negpart[gbid] = tot;
    }
}

// -------------------------------------------------------------------------
// Finalize: deterministic reduction + flag reset for next graph replay.
// -------------------------------------------------------------------------
__global__ __launch_bounds__(256) void finalize_kernel(float* out) {
    __shared__ double shp[256];
    __shared__ double shn[256];
    int tid = threadIdx.x;

    double p = 0.0, n = 0.0;
    for (int i = tid; i < NR; i += 256) p += (double)g_pos[i];
    for (int i = tid; i < NGBLK; i += 256) n += (double)g_negpart[i];
    shp[tid] = p;
    shn[tid] = n;
    if (tid < NT) g_flag[tid] = 0;   // reset ready counters for next replay
    __syncthreads();
    for (int s = 128; s; s >>= 1) {
        if (tid < s) { shp[tid] += shp[tid + s]; shn[tid] += shn[tid + s]; }
        __syncthreads();
    }
    if (tid == 0) {
        double star_mean = shn[0] / ((double)NR * (double)(NR - 1)) + 1e-8;
        double loss = -(shp[0] / (double)NR) + 64.0 * star_mean;
        out[0] = (float)loss;
    }
}

extern "C" void kernel_launch(void* const* d_in, const int* in_sizes, int n_in,
                              void* d_out, int out_size) {
    const float* z = (const float*)d_in[0];
    float* out = (float*)d_out;
    fused_main<<<NGRID, 256>>>(z);
    finalize_kernel<<<1, 256>>>(out);
}

// round 17
// speedup vs baseline: 1.0931x; 1.0931x over previous
#include <cuda_runtime.h>
#include <cuda_bf16.h>
#include <cuda_fp16.h>
#include <stdint.h>

// Problem constants
#define NR 4096
#define DIM 1024                 // bytes/row in fp8
#define NT 32                    // 128-row tiles per dim
#define NOFF 496                 // off-diagonal tiles (ti < tj)
#define NBLK 528                 // 496 off-diag + 32 diag (diag scheduled LAST)
#define BKB 64                   // K bytes per stage
#define NSTG 16                  // 1024 / 64
#define STAGE_BYTES 16384        // A 128x64B + B 128x64B
#define SMEM_TOTAL (3 * STAGE_BYTES)   // 48KB static, 3-stage ring

// Scratch (static device globals; no runtime allocation)
__device__ uint8_t g_zq[NR * DIM];   // normalized z1 * 16, e4m3 (4 MB, L2-resident)
__device__ float g_pos[NR];
__device__ float g_negpart[NBLK + 4]; // padded to float4 multiple (extra zeros)

__device__ __forceinline__ uint32_t su32(const void* p) {
    return (uint32_t)__cvta_generic_to_shared(p);
}
__device__ __forceinline__ void cpasync16(uint32_t dst, const void* g) {
    asm volatile("cp.async.cg.shared.global [%0], [%1], 16;" :: "r"(dst), "l"(g));
}
#define CP_COMMIT() asm volatile("cp.async.commit_group;")
#define CP_WAIT(n)  asm volatile("cp.async.wait_group %0;" :: "n"(n))

#define LDMX4(R, addr) \
    asm volatile("ldmatrix.sync.aligned.m8n8.x4.shared.b16 {%0,%1,%2,%3}, [%4];" \
                 : "=r"((R)[0]), "=r"((R)[1]), "=r"((R)[2]), "=r"((R)[3]) : "r"(addr))

// fp8 MMA with f16 accumulator (2 packed regs)
__device__ __forceinline__ void mma16832h(uint32_t* c, const uint32_t* a, const uint32_t* b) {
    asm volatile(
        "mma.sync.aligned.m16n8k32.row.col.f16.e4m3.e4m3.f16 "
        "{%0,%1}, {%2,%3,%4,%5}, {%6,%7}, {%0,%1};"
        : "+r"(c[0]), "+r"(c[1])
        : "r"(a[0]), "r"(a[1]), "r"(a[2]), "r"(a[3]), "r"(b[0]), "r"(b[1]));
}

// packed 2^x for two halves — ONE MUFU op per two exponentials
__device__ __forceinline__ __half2 hexp2_x2(__half2 x) {
    __half2 r;
    asm("ex2.approx.f16x2 %0, %1;"
        : "=r"(*(uint32_t*)&r) : "r"(*(const uint32_t*)&x));
    return r;
}

__device__ __forceinline__ uint32_t pack4_e4m3(float v0, float v1, float v2, float v3) {
    uint16_t h01, h23;
    asm("cvt.rn.satfinite.e4m3x2.f32 %0, %1, %2;" : "=h"(h01) : "f"(v1), "f"(v0));
    asm("cvt.rn.satfinite.e4m3x2.f32 %0, %1, %2;" : "=h"(h23) : "f"(v3), "f"(v2));
    return (uint32_t)h01 | ((uint32_t)h23 << 16);
}

// SW64 swizzle for 64B-wide rows (conflict-free ldmatrix over 8 rows)
__device__ __forceinline__ uint32_t sw64(uint32_t off) {
    return off ^ ((off >> 3) & 0x30);
}

// -------------------------------------------------------------------------
// Kernel 1: warp-per-row-pair normalize with batched loads and a 128-reg
// budget (__launch_bounds__(128,4)): occupancy is grid-limited (~28
// warps/SM), so spending registers on 16 in-flight float4 loads is free.
// -------------------------------------------------------------------------
__global__ __launch_bounds__(128, 4) void normalize_kernel(const float* __restrict__ z) {
    int warp = threadIdx.x >> 5, lane = threadIdx.x & 31;
    int row = blockIdx.x * 4 + warp;

    const float4* z1p = (const float4*)(z + (size_t)row * DIM);
    const float4* z2p = (const float4*)(z + (size_t)(row + NR) * DIM);

    float4 a[8], b[8];
    #pragma unroll
    for (int i = 0; i < 8; i++) a[i] = z1p[lane + 32 * i];
    #pragma unroll
    for (int i = 0; i < 8; i++) b[i] = z2p[lane + 32 * i];

    float s1 = 0.f, s2 = 0.f, s12 = 0.f;
    #pragma unroll
    for (int i = 0; i < 8; i++) {
        s1  += a[i].x * a[i].x + a[i].y * a[i].y + a[i].z * a[i].z + a[i].w * a[i].w;
        s2  += b[i].x * b[i].x + b[i].y * b[i].y + b[i].z * b[i].z + b[i].w * b[i].w;
        s12 += a[i].x * b[i].x + a[i].y * b[i].y + a[i].z * b[i].z + a[i].w * b[i].w;
    }
    #pragma unroll
    for (int o = 16; o; o >>= 1) {
        s1  += __shfl_xor_sync(0xFFFFFFFFu, s1, o);
        s2  += __shfl_xor_sync(0xFFFFFFFFu, s2, o);
        s12 += __shfl_xor_sync(0xFFFFFFFFu, s12, o);
    }
    float inv1 = 1.f / fmaxf(sqrtf(s1), 1e-12f);
    float inv2 = 1.f / fmaxf(sqrtf(s2), 1e-12f);
    float q1 = 16.f * inv1;

    uint32_t* dst = (uint32_t*)(g_zq + (size_t)row * DIM);
    #pragma unroll
    for (int i = 0; i < 8; i++) {
        dst[lane + 32 * i] = pack4_e4m3(a[i].x * q1, a[i].y * q1, a[i].z * q1, a[i].w * q1);
    }
    if (lane == 0) {
        float n1sq = s1 * inv1 * inv1;
        float n2sq = s2 * inv2 * inv2;
        float dp = n1sq + n2sq - 2.f * s12 * inv1 * inv2;
        g_pos[row] = logf(__expf(-0.5f * dp) + 1e-8f) + 1.f;
    }
}

// -------------------------------------------------------------------------
// Kernel 2: fp8 Gram (f16 acc) + f16x2 exp2 epilogue (R14 exact — best).
// Diag tiles scheduled LAST (drain-tail packing). 528 CTAs x 256 thr,
// 2 CTAs/SM. CTA tile 128x128; warp tile 64x32. 3-stage static ring.
// -------------------------------------------------------------------------
__global__ __launch_bounds__(256, 2) void gram_kernel() {
    __shared__ uint8_t dsm[SMEM_TOTAL];
    uint32_t smem_base = su32(dsm);
    int tid = threadIdx.x;
    int warp = tid >> 5, lane = tid & 31;
    int wr = warp >> 2, wc = warp & 3;   // warp grid 2 x 4 (rows x cols)

    // bid -> (ti, tj): off-diag (ti<tj) for bid<NOFF, diag for bid>=NOFF
    int ti, tj;
    if (blockIdx.x < NOFF) {
        int t = 0, rem = blockIdx.x;
        #pragma unroll 1
        while (rem >= NT - 1 - t) { rem -= NT - 1 - t; t++; }
        ti = t; tj = t + 1 + rem;
    } else {
        ti = tj = blockIdx.x - NOFF;
    }

    bool diag = (ti == tj);
    bool active = !(diag && (wc * 32 + 32 <= wr * 64));

    const uint8_t* Abase = g_zq + (size_t)ti * 128 * DIM;
    const uint8_t* Bbase = g_zq + (size_t)tj * 128 * DIM;

    uint32_t acc[4][4][2];   // f16x2 accumulators (= 256 * dot pairs)
    #pragma unroll
    for (int i = 0; i < 4; i++)
        #pragma unroll
        for (int j = 0; j < 4; j++) { acc[i][j][0] = 0u; acc[i][j][1] = 0u; }

    #define LOAD_STAGE(s, slot)                                                   \
        do {                                                                      \
            uint32_t base_ = smem_base + (slot) * STAGE_BYTES;                    \
            const uint8_t* Ak = Abase + (s) * BKB;                                \
            const uint8_t* Bk = Bbase + (s) * BKB;                                \
            _Pragma("unroll")                                                     \
            for (int x = tid; x < 512; x += 256) {                                \
                int r_ = x >> 2, c_ = x & 3;                                      \
                uint32_t off = sw64((uint32_t)(r_ * 64 + c_ * 16));               \
                cpasync16(base_ + off, Ak + (size_t)r_ * DIM + c_ * 16);          \
            }                                                                     \
            _Pragma("unroll")                                                     \
            for (int x = tid; x < 512; x += 256) {                                \
                int r_ = x >> 2, c_ = x & 3;                                      \
                uint32_t off = sw64((uint32_t)(r_ * 64 + c_ * 16));               \
                cpasync16(base_ + 8192 + off, Bk + (size_t)r_ * DIM + c_ * 16);   \
            }                                                                     \
            CP_COMMIT();                                                          \
        } while (0)

    LOAD_STAGE(0, 0);
    LOAD_STAGE(1, 1);
    LOAD_STAGE(2, 2);

    int slot = 0;
    #pragma unroll 1
    for (int s = 0; s < NSTG; s++) {
        if (s <= NSTG - 3)      CP_WAIT(2);
        else if (s == NSTG - 2) CP_WAIT(1);
        else                    CP_WAIT(0);
        __syncthreads();

        if (active) {
            uint32_t sa = smem_base + slot * STAGE_BYTES;
            uint32_t sb = sa + 8192;
            #pragma unroll
            for (int kk = 0; kk < 2; kk++) {
                uint32_t af[4][4];
                #pragma unroll
                for (int mi = 0; mi < 4; mi++) {
                    int r = wr * 64 + mi * 16 + (lane & 7) + ((lane >> 3) & 1) * 8;
                    int cb = kk * 32 + ((lane >> 4) & 1) * 16;
                    LDMX4(af[mi], sa + sw64((uint32_t)(r * 64 + cb)));
                }
                uint32_t bf[4][2];
                #pragma unroll
                for (int p = 0; p < 2; p++) {
                    int r = wc * 32 + p * 16 + ((lane >> 4) & 1) * 8 + (lane & 7);
                    int cb = kk * 32 + ((lane >> 3) & 1) * 16;
                    uint32_t t[4];
                    LDMX4(t, sb + sw64((uint32_t)(r * 64 + cb)));
                    bf[2 * p + 0][0] = t[0]; bf[2 * p + 0][1] = t[1];
                    bf[2 * p + 1][0] = t[2]; bf[2 * p + 1][1] = t[3];
                }
                #pragma unroll
                for (int mi = 0; mi < 4; mi++)
                    #pragma unroll
                    for (int ni = 0; ni < 4; ni++)
                        mma16832h(acc[mi][ni], af[mi], bf[ni]);
            }
        }

        if (s + 3 < NSTG) {
            __syncthreads();
            LOAD_STAGE(s + 3, slot);
        }
        slot = (slot == 2) ? 0 : slot + 1;
    }

    // ---- f16x2 epilogue: rows unit-norm -> g = exp(dot-1) = 2^(acc*k - log2e)
    const __half2 k2 = __float2half2_rn(1.44269504f / 256.f);
    const __half2 c2 = __float2half2_rn(-1.44269504f);
    __half2 hs0 = __float2half2_rn(0.f), hs1 = hs0, hs2 = hs0, hs3 = hs0;

    float local = 0.f;
    if (active) {
        if (!diag) {
            #pragma unroll
            for (int mi = 0; mi < 4; mi++)
                #pragma unroll
                for (int ni = 0; ni < 4; ni++) {
                    __half2 g0 = hexp2_x2(__hfma2(*(__half2*)&acc[mi][ni][0], k2, c2));
                    __half2 g1 = hexp2_x2(__hfma2(*(__half2*)&acc[mi][ni][1], k2, c2));
                    if (ni & 1) { hs1 = __hadd2(hs1, g0); hs3 = __hadd2(hs3, g1); }
                    else        { hs0 = __hadd2(hs0, g0); hs2 = __hadd2(hs2, g1); }
                }
        } else {
            int r0 = lane >> 2, c0 = (lane & 3) * 2;
            #pragma unroll
            for (int mi = 0; mi < 4; mi++) {
                int gi0 = wr * 64 + mi * 16 + r0;
                #pragma unroll
                for (int ni = 0; ni < 4; ni++) {
                    int gj0 = wc * 32 + ni * 8 + c0;
                    __half2 m0 = __floats2half2_rn(gj0 > gi0 ? 1.f : 0.f,
                                                   gj0 + 1 > gi0 ? 1.f : 0.f);
                    __half2 m1 = __floats2half2_rn(gj0 > gi0 + 8 ? 1.f : 0.f,
                                                   gj0 + 1 > gi0 + 8 ? 1.f : 0.f);
                    __half2 g0 = hexp2_x2(__hfma2(*(__half2*)&acc[mi][ni][0], k2, c2));
                    __half2 g1 = hexp2_x2(__hfma2(*(__half2*)&acc[mi][ni][1], k2, c2));
                    hs0 = __hfma2(g0, m0, hs0);
                    hs2 = __hfma2(g1, m1, hs2);
                }
            }
        }
        __half2 hs = __hadd2(__hadd2(hs0, hs1), __hadd2(hs2, hs3));
        local = 2.f * (__low2float(hs) + __high2float(hs));
    }

    #pragma unroll
    for (int o = 16; o; o >>= 1) local += __shfl_xor_sync(0xFFFFFFFFu, local, o);
    __shared__ float part[8];
    if (lane == 0) part[warp] = local;
    __syncthreads();
    if (tid == 0) {
        float tot = 0.f;
        #pragma unroll
        for (int i = 0; i < 8; i++) tot += part[i];
        g_negpart[blockIdx.x] = tot;
        if (blockIdx.x < 4) g_negpart[NBLK + blockIdx.x] = 0.f;  // pad zeros
    }
}

// -------------------------------------------------------------------------
// Kernel 3: deterministic finalize — float4 loads, independent partials
// (latency hidden by MLP instead of serialized scalar chains).
// -------------------------------------------------------------------------
__global__ __launch_bounds__(256) void finalize_kernel(float* out) {
    __shared__ double shp[256];
    __shared__ double shn[256];
    int tid = threadIdx.x;

    const float4* pos4 = (const float4*)g_pos;        // 1024 float4
    const float4* neg4 = (const float4*)g_negpart;    // 133 float4 (528+4 pad)

    float4 p4[4];
    #pragma unroll
    for (int i = 0; i < 4; i++) p4[i] = pos4[tid + 256 * i];
    float4 n4 = (tid < 133) ? neg4[tid] : make_float4(0.f, 0.f, 0.f, 0.f);

    double p = 0.0;
    #pragma unroll
    for (int i = 0; i < 4; i++)
        p += (double)p4[i].x + (double)p4[i].y + (double)p4[i].z + (double)p4[i].w;
    double n = (double)n4.x + (double)n4.y + (double)n4.z + (double)n4.w;

    shp[tid] = p;
    shn[tid] = n;
    __syncthreads();
    for (int s = 128; s; s >>= 1) {
        if (tid < s) { shp[tid] += shp[tid + s]; shn[tid] += shn[tid + s]; }
        __syncthreads();
    }
    if (tid == 0) {
        double star_mean = shn[0] / ((double)NR * (double)(NR - 1)) + 1e-8;
        double loss = -(shp[0] / (double)NR) + 64.0 * star_mean;
        out[0] = (float)loss;
    }
}

extern "C" void kernel_launch(void* const* d_in, const int* in_sizes, int n_in,
                              void* d_out, int out_size) {
    const float* z = (const float*)d_in[0];
    float* out = (float*)d_out;
    normalize_kernel<<<1024, 128>>>(z);
    gram_kernel<<<NBLK, 256>>>();
    finalize_kernel<<<1, 256>>>(out);
}